// round 4
// baseline (speedup 1.0000x reference)
#include <cuda_runtime.h>

#define D 128
#define EPB 32    // edges per block
#define NPB 32    // nodes per block
#define ROW2 536  // duplicated feature row: 267*2=534, pad to 536 floats
#define NODE_PAD 264
#define MAXN 50000

// Scratch (allocation-free rule: __device__ globals)
__device__ float g_agg[MAXN * D];
__device__ float g_num[MAXN * 3];
__device__ float g_cnt[MAXN];
__device__ int   g_is64;   // 1 if edge_index buffer is int64, 0 if int32

__device__ __forceinline__ float silu_f(float v) {
    return v * (1.0f / (1.0f + __expf(-v)));
}

// packed f32x2 fma: acc = a*b + acc   (SASS FFMA2, 2x fp32 throughput)
#define FMA2(acc, a, b) \
    asm("fma.rn.f32x2 %0, %1, %2, %0;" : "+l"(acc) : "l"(a), "l"(b))

__device__ __forceinline__ float lo_f(unsigned long long v) {
    return __uint_as_float((unsigned)v);
}
__device__ __forceinline__ float hi_f(unsigned long long v) {
    return __uint_as_float((unsigned)(v >> 32));
}

// Probe edge_index dtype: an int32 buffer misread as int64 yields huge values.
__global__ void detect_kernel(const void* eidx_raw, int E, int Nn) {
    const long long* p = (const long long*)eidx_raw;
    int ok = 1;
    for (int i = 0; i < 64 && i < E; i++) {
        long long v = p[i];
        if (v < 0 || v >= (long long)Nn) { ok = 0; break; }
    }
    g_is64 = ok;
}

__device__ __forceinline__ int load_idx(const void* eidx_raw, long long pos, int is64) {
    if (is64) return (int)((const long long*)eidx_raw)[pos];
    return ((const int*)eidx_raw)[pos];
}

__global__ void zero_kernel(int n_nodes) {
    int idx = blockIdx.x * blockDim.x + threadIdx.x;
    if (idx < n_nodes * D) g_agg[idx] = 0.f;
    if (idx < n_nodes * 3) g_num[idx] = 0.f;
    if (idx < n_nodes)     g_cnt[idx] = 0.f;
}

// Edge kernel: 8 warps/block, 4 edges/warp, 4 cols/thread.
// Features live DUPLICATED (f,f) in smem so LDS.64 feeds FFMA2 directly.
__global__ __launch_bounds__(256) void edge_kernel(
    const float* __restrict__ h, const float* __restrict__ x,
    const float* __restrict__ vel, const void* __restrict__ eidx_raw,
    const float* __restrict__ We1, const float* __restrict__ be1,
    const float* __restrict__ We2, const float* __restrict__ be2,
    const float* __restrict__ Wx1, const float* __restrict__ bx1,
    const float* __restrict__ Wx2, const float* __restrict__ bx2,
    float* __restrict__ out_m, int E)
{
    extern __shared__ float fs[];          // EPB * ROW2
    __shared__ int   dst_s[EPB];
    __shared__ float rel_s[EPB][3];

    const int warp = threadIdx.x >> 5;
    const int lane = threadIdx.x & 31;
    const int c0   = lane * 4;
    const int ebase = blockIdx.x * EPB;
    const int is64 = g_is64;

    bool valid[4];

    // ---- Stage features duplicated: [h_src(128), h_dst(128), d2, vps(5), vpd(5)] ----
    #pragma unroll
    for (int i = 0; i < 4; i++) {
        int el = warp * 4 + i;
        int e  = ebase + el;
        valid[i] = (e < E);
        int ec = valid[i] ? e : 0;
        int s = load_idx(eidx_raw, ec, is64);
        int d = load_idx(eidx_raw, (long long)E + ec, is64);
        float4 hs = *(const float4*)(h + (size_t)s * D + c0);
        float4 hd = *(const float4*)(h + (size_t)d * D + c0);
        float* row = fs + el * ROW2;
        *(float4*)(row + 2*c0)           = make_float4(hs.x, hs.x, hs.y, hs.y);
        *(float4*)(row + 2*c0 + 4)       = make_float4(hs.z, hs.z, hs.w, hs.w);
        *(float4*)(row + 256 + 2*c0)     = make_float4(hd.x, hd.x, hd.y, hd.y);
        *(float4*)(row + 256 + 2*c0 + 4) = make_float4(hd.z, hd.z, hd.w, hd.w);
        if (lane == 0) {
            float rx = x[s*3+0] - x[d*3+0];
            float ry = x[s*3+1] - x[d*3+1];
            float rz = x[s*3+2] - x[d*3+2];
            float d2 = rx*rx + ry*ry + rz*rz;
            float dist = fmaxf(sqrtf(d2), 1e-8f);
            float inv = 1.0f / dist;
            float ux = rx*inv, uy = ry*inv, uz = rz*inv;
            float* geo = row + 512;       // duplicated slots for k=256..266
            geo[0] = d2; geo[1] = d2;
            #pragma unroll
            for (int j = 0; j < 5; j++) {
                const float* vs = vel + (size_t)s * 15 + j * 3;
                const float* vd = vel + (size_t)d * 15 + j * 3;
                float ps = vs[0]*ux + vs[1]*uy + vs[2]*uz;
                float pd = vd[0]*ux + vd[1]*uy + vd[2]*uz;
                geo[2 + 2*j]  = ps; geo[3 + 2*j]  = ps;
                geo[12 + 2*j] = pd; geo[13 + 2*j] = pd;
            }
            dst_s[el] = d;
            rel_s[el][0] = rx; rel_s[el][1] = ry; rel_s[el][2] = rz;
        }
    }
    __syncwarp();

    const float* fr = fs + (warp * 4) * ROW2;
    unsigned long long a0[4], a1[4];   // packed (col0,col1), (col2,col3) per edge
    float y[4][4];

    // ---- phi_e layer 1: [E,267] @ We1[267,128] + be1, SiLU ----
    {
        ulonglong2 bb = *(const ulonglong2*)(be1 + c0);
        #pragma unroll
        for (int i = 0; i < 4; i++) { a0[i] = bb.x; a1[i] = bb.y; }
    }
    #pragma unroll 4
    for (int k = 0; k < 267; k++) {
        ulonglong2 w = *(const ulonglong2*)(We1 + k * D + c0);
        #pragma unroll
        for (int i = 0; i < 4; i++) {
            unsigned long long ff = *(const unsigned long long*)(fr + i * ROW2 + 2*k);
            FMA2(a0[i], ff, w.x);
            FMA2(a1[i], ff, w.y);
        }
    }
    #pragma unroll
    for (int i = 0; i < 4; i++) {
        y[i][0] = silu_f(lo_f(a0[i])); y[i][1] = silu_f(hi_f(a0[i]));
        y[i][2] = silu_f(lo_f(a1[i])); y[i][3] = silu_f(hi_f(a1[i]));
    }

    __syncwarp();   // all lanes done reading layer-1 features
    #pragma unroll
    for (int i = 0; i < 4; i++) {
        float* row = fs + (warp*4 + i) * ROW2;
        *(float4*)(row + 2*c0)     = make_float4(y[i][0], y[i][0], y[i][1], y[i][1]);
        *(float4*)(row + 2*c0 + 4) = make_float4(y[i][2], y[i][2], y[i][3], y[i][3]);
    }
    __syncwarp();

    // ---- phi_e layer 2: y1 @ We2[128,128] + be2, SiLU -> m_ij ----
    {
        ulonglong2 bb = *(const ulonglong2*)(be2 + c0);
        #pragma unroll
        for (int i = 0; i < 4; i++) { a0[i] = bb.x; a1[i] = bb.y; }
    }
    #pragma unroll 4
    for (int k = 0; k < 128; k++) {
        ulonglong2 w = *(const ulonglong2*)(We2 + k * D + c0);
        #pragma unroll
        for (int i = 0; i < 4; i++) {
            unsigned long long ff = *(const unsigned long long*)(fr + i * ROW2 + 2*k);
            FMA2(a0[i], ff, w.x);
            FMA2(a1[i], ff, w.y);
        }
    }
    #pragma unroll
    for (int i = 0; i < 4; i++) {
        y[i][0] = silu_f(lo_f(a0[i])); y[i][1] = silu_f(hi_f(a0[i]));
        y[i][2] = silu_f(lo_f(a1[i])); y[i][3] = silu_f(hi_f(a1[i]));
    }

    // store m_ij + scatter-add into agg
    #pragma unroll
    for (int i = 0; i < 4; i++) {
        if (valid[i]) {
            size_t eg = (size_t)(ebase + warp * 4 + i);
            *(float4*)(out_m + eg * D + c0) =
                make_float4(y[i][0], y[i][1], y[i][2], y[i][3]);
            int d = dst_s[warp*4 + i];
            float* ag = g_agg + (size_t)d * D + c0;
            atomicAdd(ag + 0, y[i][0]);
            atomicAdd(ag + 1, y[i][1]);
            atomicAdd(ag + 2, y[i][2]);
            atomicAdd(ag + 3, y[i][3]);
        }
    }

    __syncwarp();   // all lanes done reading y1 rows
    #pragma unroll
    for (int i = 0; i < 4; i++) {
        float* row = fs + (warp*4 + i) * ROW2;
        *(float4*)(row + 2*c0)     = make_float4(y[i][0], y[i][0], y[i][1], y[i][1]);
        *(float4*)(row + 2*c0 + 4) = make_float4(y[i][2], y[i][2], y[i][3], y[i][3]);
    }
    __syncwarp();

    // ---- phi_x layer 1: m @ Wx1[128,128] + bx1, SiLU ----
    {
        ulonglong2 bb = *(const ulonglong2*)(bx1 + c0);
        #pragma unroll
        for (int i = 0; i < 4; i++) { a0[i] = bb.x; a1[i] = bb.y; }
    }
    #pragma unroll 4
    for (int k = 0; k < 128; k++) {
        ulonglong2 w = *(const ulonglong2*)(Wx1 + k * D + c0);
        #pragma unroll
        for (int i = 0; i < 4; i++) {
            unsigned long long ff = *(const unsigned long long*)(fr + i * ROW2 + 2*k);
            FMA2(a0[i], ff, w.x);
            FMA2(a1[i], ff, w.y);
        }
    }

    // ---- phi_x layer 2: y2 @ Wx2[128,1] + bx2 -> scalar per edge ----
    float4 wx = *(const float4*)(Wx2 + c0);
    float p[4];
    #pragma unroll
    for (int i = 0; i < 4; i++) {
        float y0 = silu_f(lo_f(a0[i]));
        float y1v = silu_f(hi_f(a0[i]));
        float y2v = silu_f(lo_f(a1[i]));
        float y3v = silu_f(hi_f(a1[i]));
        p[i] = y0*wx.x + y1v*wx.y + y2v*wx.z + y3v*wx.w;
    }
    #pragma unroll
    for (int off = 16; off > 0; off >>= 1) {
        #pragma unroll
        for (int i = 0; i < 4; i++)
            p[i] += __shfl_xor_sync(0xffffffffu, p[i], off);
    }
    if (lane == 0) {
        float bx2v = bx2[0];
        #pragma unroll
        for (int i = 0; i < 4; i++) {
            if (valid[i]) {
                float w = p[i] + bx2v;
                int el = warp*4 + i;
                int d = dst_s[el];
                atomicAdd(&g_num[d*3 + 0], rel_s[el][0] * w);
                atomicAdd(&g_num[d*3 + 1], rel_s[el][1] * w);
                atomicAdd(&g_num[d*3 + 2], rel_s[el][2] * w);
                atomicAdd(&g_cnt[d], 1.0f);
            }
        }
    }
}

// Node kernel: phi_h([h, agg]) + residual + LayerNorm, plus x update.
__global__ __launch_bounds__(256) void node_kernel(
    const float* __restrict__ h, const float* __restrict__ x,
    const float* __restrict__ Wh1, const float* __restrict__ bh1,
    const float* __restrict__ Wh2, const float* __restrict__ bh2,
    const float* __restrict__ gamma, const float* __restrict__ beta,
    float* __restrict__ out_h, float* __restrict__ out_x, int Nn)
{
    __shared__ float fs[NPB * NODE_PAD];
    const int warp = threadIdx.x >> 5;
    const int lane = threadIdx.x & 31;
    const int c0   = lane * 4;
    const int nbase = blockIdx.x * NPB;

    bool valid[4];
    int nidx[4];
    #pragma unroll
    for (int i = 0; i < 4; i++) {
        int nl = warp * 4 + i;
        int n  = nbase + nl;
        valid[i] = (n < Nn);
        int nc = valid[i] ? n : 0;
        nidx[i] = nc;
        float4 hh = *(const float4*)(h + (size_t)nc * D + c0);
        float4 ag = *(const float4*)(g_agg + (size_t)nc * D + c0);
        *(float4*)(fs + nl * NODE_PAD + c0)       = hh;
        *(float4*)(fs + nl * NODE_PAD + 128 + c0) = ag;
    }
    __syncwarp();

    const float* fr = fs + (warp * 4) * NODE_PAD;
    float acc[4][4];

    // phi_h layer 1: [h, agg] @ Wh1[256,128] + bh1, SiLU
    {
        float4 b = *(const float4*)(bh1 + c0);
        #pragma unroll
        for (int i = 0; i < 4; i++) {
            acc[i][0] = b.x; acc[i][1] = b.y; acc[i][2] = b.z; acc[i][3] = b.w;
        }
    }
    #pragma unroll 4
    for (int k = 0; k < 256; k++) {
        float4 w = *(const float4*)(Wh1 + k * D + c0);
        #pragma unroll
        for (int i = 0; i < 4; i++) {
            float f = fr[i * NODE_PAD + k];
            acc[i][0] = fmaf(f, w.x, acc[i][0]);
            acc[i][1] = fmaf(f, w.y, acc[i][1]);
            acc[i][2] = fmaf(f, w.z, acc[i][2]);
            acc[i][3] = fmaf(f, w.w, acc[i][3]);
        }
    }
    #pragma unroll
    for (int i = 0; i < 4; i++)
        #pragma unroll
        for (int q = 0; q < 4; q++) acc[i][q] = silu_f(acc[i][q]);

    __syncwarp();
    #pragma unroll
    for (int i = 0; i < 4; i++)
        *(float4*)(fs + (warp*4 + i) * NODE_PAD + c0) =
            make_float4(acc[i][0], acc[i][1], acc[i][2], acc[i][3]);
    __syncwarp();

    // phi_h layer 2: y @ Wh2[128,128] + bh2
    {
        float4 b = *(const float4*)(bh2 + c0);
        #pragma unroll
        for (int i = 0; i < 4; i++) {
            acc[i][0] = b.x; acc[i][1] = b.y; acc[i][2] = b.z; acc[i][3] = b.w;
        }
    }
    #pragma unroll 4
    for (int k = 0; k < 128; k++) {
        float4 w = *(const float4*)(Wh2 + k * D + c0);
        #pragma unroll
        for (int i = 0; i < 4; i++) {
            float f = fr[i * NODE_PAD + k];
            acc[i][0] = fmaf(f, w.x, acc[i][0]);
            acc[i][1] = fmaf(f, w.y, acc[i][1]);
            acc[i][2] = fmaf(f, w.z, acc[i][2]);
            acc[i][3] = fmaf(f, w.w, acc[i][3]);
        }
    }

    // residual + LayerNorm (warp-level row reduce)
    float hn[4][4];
    float mu[4], rstd[4];
    #pragma unroll
    for (int i = 0; i < 4; i++) {
        float4 hh = *(const float4*)(h + (size_t)nidx[i] * D + c0);
        hn[i][0] = hh.x + acc[i][0];
        hn[i][1] = hh.y + acc[i][1];
        hn[i][2] = hh.z + acc[i][2];
        hn[i][3] = hh.w + acc[i][3];
        float s1 = hn[i][0] + hn[i][1] + hn[i][2] + hn[i][3];
        float s2 = hn[i][0]*hn[i][0] + hn[i][1]*hn[i][1]
                 + hn[i][2]*hn[i][2] + hn[i][3]*hn[i][3];
        #pragma unroll
        for (int off = 16; off > 0; off >>= 1) {
            s1 += __shfl_xor_sync(0xffffffffu, s1, off);
            s2 += __shfl_xor_sync(0xffffffffu, s2, off);
        }
        mu[i] = s1 * (1.0f / 128.0f);
        float var = s2 * (1.0f / 128.0f) - mu[i]*mu[i];
        rstd[i] = rsqrtf(var + 1e-5f);
    }
    float4 g = *(const float4*)(gamma + c0);
    float4 b = *(const float4*)(beta + c0);
    #pragma unroll
    for (int i = 0; i < 4; i++) {
        if (valid[i]) {
            float4 o;
            o.x = (hn[i][0] - mu[i]) * rstd[i] * g.x + b.x;
            o.y = (hn[i][1] - mu[i]) * rstd[i] * g.y + b.y;
            o.z = (hn[i][2] - mu[i]) * rstd[i] * g.z + b.z;
            o.w = (hn[i][3] - mu[i]) * rstd[i] * g.w + b.w;
            *(float4*)(out_h + (size_t)nidx[i] * D + c0) = o;
        }
    }

    // x update: x + num / max(cnt, 1)
    if (lane == 0) {
        #pragma unroll
        for (int i = 0; i < 4; i++) {
            if (valid[i]) {
                int n = nidx[i];
                float cnt = g_cnt[n];
                float inv = 1.0f / fmaxf(cnt, 1.0f);
                out_x[n*3 + 0] = x[n*3 + 0] + g_num[n*3 + 0] * inv;
                out_x[n*3 + 1] = x[n*3 + 1] + g_num[n*3 + 1] * inv;
                out_x[n*3 + 2] = x[n*3 + 2] + g_num[n*3 + 2] * inv;
            }
        }
    }
}

extern "C" void kernel_launch(void* const* d_in, const int* in_sizes, int n_in,
                              void* d_out, int out_size) {
    const float* h    = (const float*)d_in[0];
    const float* x    = (const float*)d_in[1];
    const float* vel  = (const float*)d_in[2];
    const void*  eidx = d_in[3];
    const float* We1 = (const float*)d_in[4],  *be1 = (const float*)d_in[5];
    const float* We2 = (const float*)d_in[6],  *be2 = (const float*)d_in[7];
    const float* Wx1 = (const float*)d_in[8],  *bx1 = (const float*)d_in[9];
    const float* Wx2 = (const float*)d_in[10], *bx2 = (const float*)d_in[11];
    const float* Wh1 = (const float*)d_in[12], *bh1 = (const float*)d_in[13];
    const float* Wh2 = (const float*)d_in[14], *bh2 = (const float*)d_in[15];
    const float* gamma = (const float*)d_in[16], *beta = (const float*)d_in[17];

    int Nn = in_sizes[0] / D;
    int E  = in_sizes[3] / 2;

    float* out   = (float*)d_out;
    float* out_h = out;
    float* out_x = out + (size_t)Nn * D;
    float* out_m = out_x + (size_t)Nn * 3;

    const int edge_smem = EPB * ROW2 * (int)sizeof(float);   // 68608 B
    cudaFuncSetAttribute(edge_kernel,
                         cudaFuncAttributeMaxDynamicSharedMemorySize, edge_smem);

    detect_kernel<<<1, 1>>>(eidx, E, Nn);
    zero_kernel<<<(Nn * D + 255) / 256, 256>>>(Nn);
    edge_kernel<<<(E + EPB - 1) / EPB, 256, edge_smem>>>(h, x, vel, eidx,
                                              We1, be1, We2, be2,
                                              Wx1, bx1, Wx2, bx2,
                                              out_m, E);
    node_kernel<<<(Nn + NPB - 1) / NPB, 256>>>(h, x, Wh1, bh1, Wh2, bh2,
                                               gamma, beta, out_h, out_x, Nn);
}

// round 5
// speedup vs baseline: 1.9873x; 1.9873x over previous
#include <cuda_runtime.h>

#define D 128
#define EPB 32    // edges per block
#define NPB 32    // nodes per block
#define Y_PAD 136 // y1 row pad (128 data)
#define NODE_PAD 264
#define MAXN 50000

// Scratch (allocation-free rule: __device__ globals)
__device__ float g_agg[MAXN * D];
__device__ float g_num[MAXN * 3];
__device__ float g_cnt[MAXN];
__device__ float g_U[MAXN * D];   // h @ We1[0:128,:] + be1
__device__ float g_V[MAXN * D];   // h @ We1[128:256,:]
__device__ int   g_is64;

__device__ __forceinline__ float silu_f(float v) {
    return v * (1.0f / (1.0f + __expf(-v)));
}

// Probe edge_index dtype: int32 buffer misread as int64 yields huge values.
__global__ void detect_kernel(const void* eidx_raw, int E, int Nn) {
    const long long* p = (const long long*)eidx_raw;
    int ok = 1;
    for (int i = 0; i < 64 && i < E; i++) {
        long long v = p[i];
        if (v < 0 || v >= (long long)Nn) { ok = 0; break; }
    }
    g_is64 = ok;
}

__device__ __forceinline__ int load_idx(const void* eidx_raw, long long pos, int is64) {
    if (is64) return (int)((const long long*)eidx_raw)[pos];
    return ((const int*)eidx_raw)[pos];
}

__global__ void zero_kernel(int n_nodes) {
    int idx = blockIdx.x * blockDim.x + threadIdx.x;
    if (idx < n_nodes * D) g_agg[idx] = 0.f;
    if (idx < n_nodes * 3) g_num[idx] = 0.f;
    if (idx < n_nodes)     g_cnt[idx] = 0.f;
}

// Per-node precompute: U = h @ We1_top + be1, V = h @ We1_bot.
// 8 warps/block, 4 nodes/warp, 4 cols/thread (same scheme as node kernel).
__global__ __launch_bounds__(256) void precompute_kernel(
    const float* __restrict__ h, const float* __restrict__ We1,
    const float* __restrict__ be1, int Nn)
{
    __shared__ float fs[NPB * Y_PAD];
    const int warp = threadIdx.x >> 5;
    const int lane = threadIdx.x & 31;
    const int c0   = lane * 4;
    const int nbase = blockIdx.x * NPB;

    int nidx[4]; bool valid[4];
    #pragma unroll
    for (int i = 0; i < 4; i++) {
        int nl = warp * 4 + i;
        int n  = nbase + nl;
        valid[i] = (n < Nn);
        nidx[i] = valid[i] ? n : 0;
        float4 hh = *(const float4*)(h + (size_t)nidx[i] * D + c0);
        *(float4*)(fs + nl * Y_PAD + c0) = hh;
    }
    __syncwarp();

    const float* fr = fs + (warp * 4) * Y_PAD;
    float acc[4][4];

    // U = h @ We1[0:128] + be1
    {
        float4 b = *(const float4*)(be1 + c0);
        #pragma unroll
        for (int i = 0; i < 4; i++) {
            acc[i][0] = b.x; acc[i][1] = b.y; acc[i][2] = b.z; acc[i][3] = b.w;
        }
    }
    #pragma unroll 4
    for (int k = 0; k < 128; k++) {
        float4 w = *(const float4*)(We1 + k * D + c0);
        #pragma unroll
        for (int i = 0; i < 4; i++) {
            float f = fr[i * Y_PAD + k];
            acc[i][0] = fmaf(f, w.x, acc[i][0]);
            acc[i][1] = fmaf(f, w.y, acc[i][1]);
            acc[i][2] = fmaf(f, w.z, acc[i][2]);
            acc[i][3] = fmaf(f, w.w, acc[i][3]);
        }
    }
    #pragma unroll
    for (int i = 0; i < 4; i++)
        if (valid[i])
            *(float4*)(g_U + (size_t)nidx[i] * D + c0) =
                make_float4(acc[i][0], acc[i][1], acc[i][2], acc[i][3]);

    // V = h @ We1[128:256]
    #pragma unroll
    for (int i = 0; i < 4; i++) {
        acc[i][0] = 0.f; acc[i][1] = 0.f; acc[i][2] = 0.f; acc[i][3] = 0.f;
    }
    #pragma unroll 4
    for (int k = 0; k < 128; k++) {
        float4 w = *(const float4*)(We1 + (128 + k) * D + c0);
        #pragma unroll
        for (int i = 0; i < 4; i++) {
            float f = fr[i * Y_PAD + k];
            acc[i][0] = fmaf(f, w.x, acc[i][0]);
            acc[i][1] = fmaf(f, w.y, acc[i][1]);
            acc[i][2] = fmaf(f, w.z, acc[i][2]);
            acc[i][3] = fmaf(f, w.w, acc[i][3]);
        }
    }
    #pragma unroll
    for (int i = 0; i < 4; i++)
        if (valid[i])
            *(float4*)(g_V + (size_t)nidx[i] * D + c0) =
                make_float4(acc[i][0], acc[i][1], acc[i][2], acc[i][3]);
}

// Edge kernel: 8 warps/block, 4 edges/warp, 4 cols/thread.
// phi_e L1 = U[src] + V[dst] + geo(11) @ We1[256:267] (precomputed factorization).
__global__ __launch_bounds__(256) void edge_kernel(
    const float* __restrict__ x,
    const float* __restrict__ vel, const void* __restrict__ eidx_raw,
    const float* __restrict__ We1,
    const float* __restrict__ We2, const float* __restrict__ be2,
    const float* __restrict__ Wx1, const float* __restrict__ bx1,
    const float* __restrict__ Wx2, const float* __restrict__ bx2,
    float* __restrict__ out_m, int E)
{
    __shared__ float ys[EPB * Y_PAD];
    __shared__ float geo_s[EPB][12];
    __shared__ int   dst_s[EPB];
    __shared__ float rel_s[EPB][3];

    const int warp = threadIdx.x >> 5;
    const int lane = threadIdx.x & 31;
    const int c0   = lane * 4;
    const int ebase = blockIdx.x * EPB;
    const int is64 = g_is64;

    bool valid[4];
    float acc[4][4];

    // ---- Stage: acc init = U[src] + V[dst]; lane0 computes geo ----
    #pragma unroll
    for (int i = 0; i < 4; i++) {
        int el = warp * 4 + i;
        int e  = ebase + el;
        valid[i] = (e < E);
        int ec = valid[i] ? e : 0;
        int s = load_idx(eidx_raw, ec, is64);
        int d = load_idx(eidx_raw, (long long)E + ec, is64);
        float4 u = *(const float4*)(g_U + (size_t)s * D + c0);
        float4 v = *(const float4*)(g_V + (size_t)d * D + c0);
        acc[i][0] = u.x + v.x;
        acc[i][1] = u.y + v.y;
        acc[i][2] = u.z + v.z;
        acc[i][3] = u.w + v.w;
        if (lane == 0) {
            float rx = x[s*3+0] - x[d*3+0];
            float ry = x[s*3+1] - x[d*3+1];
            float rz = x[s*3+2] - x[d*3+2];
            float d2 = rx*rx + ry*ry + rz*rz;
            float dist = fmaxf(sqrtf(d2), 1e-8f);
            float inv = 1.0f / dist;
            float ux = rx*inv, uy = ry*inv, uz = rz*inv;
            geo_s[el][0] = d2;
            #pragma unroll
            for (int j = 0; j < 5; j++) {
                const float* vs = vel + (size_t)s * 15 + j * 3;
                const float* vd = vel + (size_t)d * 15 + j * 3;
                geo_s[el][1 + j] = vs[0]*ux + vs[1]*uy + vs[2]*uz;
                geo_s[el][6 + j] = vd[0]*ux + vd[1]*uy + vd[2]*uz;
            }
            dst_s[el] = d;
            rel_s[el][0] = rx; rel_s[el][1] = ry; rel_s[el][2] = rz;
        }
    }
    __syncwarp();

    // ---- geo part of L1: 11 k-iters over We1 rows 256..266, then SiLU ----
    #pragma unroll
    for (int k = 0; k < 11; k++) {
        float4 w = *(const float4*)(We1 + (256 + k) * D + c0);
        #pragma unroll
        for (int i = 0; i < 4; i++) {
            float f = geo_s[warp*4 + i][k];
            acc[i][0] = fmaf(f, w.x, acc[i][0]);
            acc[i][1] = fmaf(f, w.y, acc[i][1]);
            acc[i][2] = fmaf(f, w.z, acc[i][2]);
            acc[i][3] = fmaf(f, w.w, acc[i][3]);
        }
    }
    #pragma unroll
    for (int i = 0; i < 4; i++)
        #pragma unroll
        for (int q = 0; q < 4; q++) acc[i][q] = silu_f(acc[i][q]);

    // stash y1
    #pragma unroll
    for (int i = 0; i < 4; i++)
        *(float4*)(ys + (warp*4 + i) * Y_PAD + c0) =
            make_float4(acc[i][0], acc[i][1], acc[i][2], acc[i][3]);
    __syncwarp();

    const float* fr = ys + (warp * 4) * Y_PAD;

    // ---- phi_e layer 2: y1 @ We2 + be2, SiLU -> m_ij ----
    {
        float4 b = *(const float4*)(be2 + c0);
        #pragma unroll
        for (int i = 0; i < 4; i++) {
            acc[i][0] = b.x; acc[i][1] = b.y; acc[i][2] = b.z; acc[i][3] = b.w;
        }
    }
    #pragma unroll 4
    for (int k = 0; k < 128; k++) {
        float4 w = *(const float4*)(We2 + k * D + c0);
        #pragma unroll
        for (int i = 0; i < 4; i++) {
            float f = fr[i * Y_PAD + k];
            acc[i][0] = fmaf(f, w.x, acc[i][0]);
            acc[i][1] = fmaf(f, w.y, acc[i][1]);
            acc[i][2] = fmaf(f, w.z, acc[i][2]);
            acc[i][3] = fmaf(f, w.w, acc[i][3]);
        }
    }
    #pragma unroll
    for (int i = 0; i < 4; i++)
        #pragma unroll
        for (int q = 0; q < 4; q++) acc[i][q] = silu_f(acc[i][q]);

    // store m_ij + scatter-add into agg
    #pragma unroll
    for (int i = 0; i < 4; i++) {
        if (valid[i]) {
            size_t eg = (size_t)(ebase + warp * 4 + i);
            *(float4*)(out_m + eg * D + c0) =
                make_float4(acc[i][0], acc[i][1], acc[i][2], acc[i][3]);
            int d = dst_s[warp*4 + i];
            float* ag = g_agg + (size_t)d * D + c0;
            atomicAdd(ag + 0, acc[i][0]);
            atomicAdd(ag + 1, acc[i][1]);
            atomicAdd(ag + 2, acc[i][2]);
            atomicAdd(ag + 3, acc[i][3]);
        }
    }

    __syncwarp();   // lanes done reading y1
    #pragma unroll
    for (int i = 0; i < 4; i++)
        *(float4*)(ys + (warp*4 + i) * Y_PAD + c0) =
            make_float4(acc[i][0], acc[i][1], acc[i][2], acc[i][3]);
    __syncwarp();

    // ---- phi_x layer 1: m @ Wx1 + bx1 ----
    {
        float4 b = *(const float4*)(bx1 + c0);
        #pragma unroll
        for (int i = 0; i < 4; i++) {
            acc[i][0] = b.x; acc[i][1] = b.y; acc[i][2] = b.z; acc[i][3] = b.w;
        }
    }
    #pragma unroll 4
    for (int k = 0; k < 128; k++) {
        float4 w = *(const float4*)(Wx1 + k * D + c0);
        #pragma unroll
        for (int i = 0; i < 4; i++) {
            float f = fr[i * Y_PAD + k];
            acc[i][0] = fmaf(f, w.x, acc[i][0]);
            acc[i][1] = fmaf(f, w.y, acc[i][1]);
            acc[i][2] = fmaf(f, w.z, acc[i][2]);
            acc[i][3] = fmaf(f, w.w, acc[i][3]);
        }
    }

    // ---- phi_x layer 2: silu(y2) @ Wx2 + bx2 -> scalar per edge ----
    float4 wx = *(const float4*)(Wx2 + c0);
    float p[4];
    #pragma unroll
    for (int i = 0; i < 4; i++) {
        float y0 = silu_f(acc[i][0]);
        float y1v = silu_f(acc[i][1]);
        float y2v = silu_f(acc[i][2]);
        float y3v = silu_f(acc[i][3]);
        p[i] = y0*wx.x + y1v*wx.y + y2v*wx.z + y3v*wx.w;
    }
    #pragma unroll
    for (int off = 16; off > 0; off >>= 1) {
        #pragma unroll
        for (int i = 0; i < 4; i++)
            p[i] += __shfl_xor_sync(0xffffffffu, p[i], off);
    }
    if (lane == 0) {
        float bx2v = bx2[0];
        #pragma unroll
        for (int i = 0; i < 4; i++) {
            if (valid[i]) {
                float w = p[i] + bx2v;
                int el = warp*4 + i;
                int d = dst_s[el];
                atomicAdd(&g_num[d*3 + 0], rel_s[el][0] * w);
                atomicAdd(&g_num[d*3 + 1], rel_s[el][1] * w);
                atomicAdd(&g_num[d*3 + 2], rel_s[el][2] * w);
                atomicAdd(&g_cnt[d], 1.0f);
            }
        }
    }
}

// Node kernel: phi_h([h, agg]) + residual + LayerNorm, plus x update.
__global__ __launch_bounds__(256) void node_kernel(
    const float* __restrict__ h, const float* __restrict__ x,
    const float* __restrict__ Wh1, const float* __restrict__ bh1,
    const float* __restrict__ Wh2, const float* __restrict__ bh2,
    const float* __restrict__ gamma, const float* __restrict__ beta,
    float* __restrict__ out_h, float* __restrict__ out_x, int Nn)
{
    __shared__ float fs[NPB * NODE_PAD];
    const int warp = threadIdx.x >> 5;
    const int lane = threadIdx.x & 31;
    const int c0   = lane * 4;
    const int nbase = blockIdx.x * NPB;

    bool valid[4];
    int nidx[4];
    #pragma unroll
    for (int i = 0; i < 4; i++) {
        int nl = warp * 4 + i;
        int n  = nbase + nl;
        valid[i] = (n < Nn);
        int nc = valid[i] ? n : 0;
        nidx[i] = nc;
        float4 hh = *(const float4*)(h + (size_t)nc * D + c0);
        float4 ag = *(const float4*)(g_agg + (size_t)nc * D + c0);
        *(float4*)(fs + nl * NODE_PAD + c0)       = hh;
        *(float4*)(fs + nl * NODE_PAD + 128 + c0) = ag;
    }
    __syncwarp();

    const float* fr = fs + (warp * 4) * NODE_PAD;
    float acc[4][4];

    // phi_h layer 1: [h, agg] @ Wh1 + bh1, SiLU
    {
        float4 b = *(const float4*)(bh1 + c0);
        #pragma unroll
        for (int i = 0; i < 4; i++) {
            acc[i][0] = b.x; acc[i][1] = b.y; acc[i][2] = b.z; acc[i][3] = b.w;
        }
    }
    #pragma unroll 4
    for (int k = 0; k < 256; k++) {
        float4 w = *(const float4*)(Wh1 + k * D + c0);
        #pragma unroll
        for (int i = 0; i < 4; i++) {
            float f = fr[i * NODE_PAD + k];
            acc[i][0] = fmaf(f, w.x, acc[i][0]);
            acc[i][1] = fmaf(f, w.y, acc[i][1]);
            acc[i][2] = fmaf(f, w.z, acc[i][2]);
            acc[i][3] = fmaf(f, w.w, acc[i][3]);
        }
    }
    #pragma unroll
    for (int i = 0; i < 4; i++)
        #pragma unroll
        for (int q = 0; q < 4; q++) acc[i][q] = silu_f(acc[i][q]);

    __syncwarp();
    #pragma unroll
    for (int i = 0; i < 4; i++)
        *(float4*)(fs + (warp*4 + i) * NODE_PAD + c0) =
            make_float4(acc[i][0], acc[i][1], acc[i][2], acc[i][3]);
    __syncwarp();

    // phi_h layer 2: y @ Wh2 + bh2
    {
        float4 b = *(const float4*)(bh2 + c0);
        #pragma unroll
        for (int i = 0; i < 4; i++) {
            acc[i][0] = b.x; acc[i][1] = b.y; acc[i][2] = b.z; acc[i][3] = b.w;
        }
    }
    #pragma unroll 4
    for (int k = 0; k < 128; k++) {
        float4 w = *(const float4*)(Wh2 + k * D + c0);
        #pragma unroll
        for (int i = 0; i < 4; i++) {
            float f = fr[i * NODE_PAD + k];
            acc[i][0] = fmaf(f, w.x, acc[i][0]);
            acc[i][1] = fmaf(f, w.y, acc[i][1]);
            acc[i][2] = fmaf(f, w.z, acc[i][2]);
            acc[i][3] = fmaf(f, w.w, acc[i][3]);
        }
    }

    // residual + LayerNorm (warp-level row reduce)
    float hn[4][4];
    float mu[4], rstd[4];
    #pragma unroll
    for (int i = 0; i < 4; i++) {
        float4 hh = *(const float4*)(h + (size_t)nidx[i] * D + c0);
        hn[i][0] = hh.x + acc[i][0];
        hn[i][1] = hh.y + acc[i][1];
        hn[i][2] = hh.z + acc[i][2];
        hn[i][3] = hh.w + acc[i][3];
        float s1 = hn[i][0] + hn[i][1] + hn[i][2] + hn[i][3];
        float s2 = hn[i][0]*hn[i][0] + hn[i][1]*hn[i][1]
                 + hn[i][2]*hn[i][2] + hn[i][3]*hn[i][3];
        #pragma unroll
        for (int off = 16; off > 0; off >>= 1) {
            s1 += __shfl_xor_sync(0xffffffffu, s1, off);
            s2 += __shfl_xor_sync(0xffffffffu, s2, off);
        }
        mu[i] = s1 * (1.0f / 128.0f);
        float var = s2 * (1.0f / 128.0f) - mu[i]*mu[i];
        rstd[i] = rsqrtf(var + 1e-5f);
    }
    float4 g = *(const float4*)(gamma + c0);
    float4 b = *(const float4*)(beta + c0);
    #pragma unroll
    for (int i = 0; i < 4; i++) {
        if (valid[i]) {
            float4 o;
            o.x = (hn[i][0] - mu[i]) * rstd[i] * g.x + b.x;
            o.y = (hn[i][1] - mu[i]) * rstd[i] * g.y + b.y;
            o.z = (hn[i][2] - mu[i]) * rstd[i] * g.z + b.z;
            o.w = (hn[i][3] - mu[i]) * rstd[i] * g.w + b.w;
            *(float4*)(out_h + (size_t)nidx[i] * D + c0) = o;
        }
    }

    // x update: x + num / max(cnt, 1)
    if (lane == 0) {
        #pragma unroll
        for (int i = 0; i < 4; i++) {
            if (valid[i]) {
                int n = nidx[i];
                float cnt = g_cnt[n];
                float inv = 1.0f / fmaxf(cnt, 1.0f);
                out_x[n*3 + 0] = x[n*3 + 0] + g_num[n*3 + 0] * inv;
                out_x[n*3 + 1] = x[n*3 + 1] + g_num[n*3 + 1] * inv;
                out_x[n*3 + 2] = x[n*3 + 2] + g_num[n*3 + 2] * inv;
            }
        }
    }
}

extern "C" void kernel_launch(void* const* d_in, const int* in_sizes, int n_in,
                              void* d_out, int out_size) {
    const float* h    = (const float*)d_in[0];
    const float* x    = (const float*)d_in[1];
    const float* vel  = (const float*)d_in[2];
    const void*  eidx = d_in[3];
    const float* We1 = (const float*)d_in[4],  *be1 = (const float*)d_in[5];
    const float* We2 = (const float*)d_in[6],  *be2 = (const float*)d_in[7];
    const float* Wx1 = (const float*)d_in[8],  *bx1 = (const float*)d_in[9];
    const float* Wx2 = (const float*)d_in[10], *bx2 = (const float*)d_in[11];
    const float* Wh1 = (const float*)d_in[12], *bh1 = (const float*)d_in[13];
    const float* Wh2 = (const float*)d_in[14], *bh2 = (const float*)d_in[15];
    const float* gamma = (const float*)d_in[16], *beta = (const float*)d_in[17];

    int Nn = in_sizes[0] / D;
    int E  = in_sizes[3] / 2;

    float* out   = (float*)d_out;
    float* out_h = out;
    float* out_x = out + (size_t)Nn * D;
    float* out_m = out_x + (size_t)Nn * 3;

    detect_kernel<<<1, 1>>>(eidx, E, Nn);
    zero_kernel<<<(Nn * D + 255) / 256, 256>>>(Nn);
    precompute_kernel<<<(Nn + NPB - 1) / NPB, 256>>>(h, We1, be1, Nn);
    edge_kernel<<<(E + EPB - 1) / EPB, 256>>>(x, vel, eidx,
                                              We1, We2, be2,
                                              Wx1, bx1, Wx2, bx2,
                                              out_m, E);
    node_kernel<<<(Nn + NPB - 1) / NPB, 256>>>(h, x, Wh1, bh1, Wh2, bh2,
                                               gamma, beta, out_h, out_x, Nn);
}